// round 6
// baseline (speedup 1.0000x reference)
#include <cuda_runtime.h>
#include <cuda_bf16.h>
#include <cstdint>

#define BB 512
#define SS 200
#define HH 256
#define MROWS (BB * SS)        // 102400 = 800 * 128
#define MTILES 800
#define KCH 4                  // K chunks of 64
#define BLK_ELEMS (128 * 64)   // one swizzled block (bf16) = 16KB

// ---------------- scratch (no cudaMalloc allowed) ----------------
__device__ float g_l[BB * HH];
__device__ float g_sc[MROWS];
__device__ __align__(128) __nv_bfloat16 g_Uhi[2 * KCH * BLK_ELEMS];
__device__ __align__(128) __nv_bfloat16 g_Ulo[2 * KCH * BLK_ELEMS];

// ---------------- helpers ----------------
__device__ __forceinline__ uint32_t smem_u32(const void* p) {
    uint32_t a;
    asm("{ .reg .u64 t; cvta.to.shared.u64 t, %1; cvt.u32.u64 %0, t; }" : "=r"(a) : "l"(p));
    return a;
}
__device__ __forceinline__ uint32_t sw128(uint32_t o) { return o ^ ((o >> 3) & 0x70); }

__device__ __forceinline__ uint32_t pack_bf2(float x, float y) {
    uint32_t a = (uint32_t)__bfloat16_as_ushort(__float2bfloat16_rn(x));
    uint32_t b = (uint32_t)__bfloat16_as_ushort(__float2bfloat16_rn(y));
    return a | (b << 16);
}

// in-register split of a float2 into bf16 hi pair + bf16 lo pair
__device__ __forceinline__ void cvt_hilo(float2 v, uint32_t& hi, uint32_t& lo) {
    __nv_bfloat162 hb = __float22bfloat162_rn(v);
    hi = *(uint32_t*)&hb;
    float h0 = __int_as_float(hi << 16);
    float h1 = __int_as_float(hi & 0xffff0000u);
    float2 l;
    l.x = v.x - h0;
    l.y = v.y - h1;
    __nv_bfloat162 lb = __float22bfloat162_rn(l);
    lo = *(uint32_t*)&lb;
}

// MUFU-free tanh (FMA/ALU pipes only); |err| <= ~3.4e-5
__device__ __forceinline__ float tanh_fma(float x) {
    float t = fminf(fabsf(x), 5.5f) * 2.8853900817779268f;  // 2*log2(e)*|x|
    int n = __float2int_rn(t);
    float f = t - (float)n;
    float p = 1.5403530393381608e-4f;
    p = fmaf(p, f, 1.3333558146428443e-3f);
    p = fmaf(p, f, 9.6181291076284772e-3f);
    p = fmaf(p, f, 5.5504108664821580e-2f);
    p = fmaf(p, f, 2.4022650695910071e-1f);
    p = fmaf(p, f, 6.9314718055994531e-1f);
    p = fmaf(p, f, 1.0f);
    float E = __int_as_float(__float_as_int(p) + (n << 23)); // e^{2|x|}
    float D = E + 1.0f;
    float r = __int_as_float(0x7EF311C3 - __float_as_int(D));
    r = r * fmaf(-D, r, 2.0f);
    r = r * fmaf(-D, r, 2.0f);
    r = r * fmaf(-D, r, 2.0f);
    float y = fmaf(-2.0f, r, 1.0f);
    return copysignf(y, x);
}

__device__ __forceinline__ void ldsm4(uint32_t* r, uint32_t addr) {
    asm volatile("ldmatrix.sync.aligned.m8n8.x4.shared.b16 {%0,%1,%2,%3}, [%4];"
                 : "=r"(r[0]), "=r"(r[1]), "=r"(r[2]), "=r"(r[3]) : "r"(addr));
}
__device__ __forceinline__ void mma_bf16(float* c, const uint32_t* a, uint32_t b0, uint32_t b1) {
    asm volatile(
        "mma.sync.aligned.m16n8k16.row.col.f32.bf16.bf16.f32 "
        "{%0,%1,%2,%3}, {%4,%5,%6,%7}, {%8,%9}, {%0,%1,%2,%3};"
        : "+f"(c[0]), "+f"(c[1]), "+f"(c[2]), "+f"(c[3])
        : "r"(a[0]), "r"(a[1]), "r"(a[2]), "r"(a[3]), "r"(b0), "r"(b1));
}
#define CPA16(dst, src) \
    asm volatile("cp.async.cg.shared.global [%0], [%1], 16;" :: "r"(dst), "l"(src))

// ---------------------------------------------------------------------------
// conv (U only, 8 CTAs): fp32 -> bf16 (hi, lo) pre-swizzled SW128 128x64 blocks
// ---------------------------------------------------------------------------
__global__ void __launch_bounds__(128) conv_kernel(const float* __restrict__ S,
                                                   __nv_bfloat16* __restrict__ DH,
                                                   __nv_bfloat16* __restrict__ DL) {
    const int blk = blockIdx.x;
    const int mt = blk >> 2;
    const int c = blk & 3;
    const int tid = threadIdx.x;
    char* dh = (char*)(DH + (size_t)blk * BLK_ELEMS);
    char* dl = (char*)(DL + (size_t)blk * BLK_ELEMS);

#pragma unroll 4
    for (int it = 0; it < 16; it++) {
        int f = it * 128 + tid;
        int row = f >> 4;
        int q = f & 15;
        float4 v = *(const float4*)(S + ((size_t)(mt * 128 + row)) * HH + c * 64 + q * 4);
        float4 h;
        h.x = __bfloat162float(__float2bfloat16_rn(v.x));
        h.y = __bfloat162float(__float2bfloat16_rn(v.y));
        h.z = __bfloat162float(__float2bfloat16_rn(v.z));
        h.w = __bfloat162float(__float2bfloat16_rn(v.w));
        uint2 ph, pl;
        ph.x = pack_bf2(v.x, v.y);
        ph.y = pack_bf2(v.z, v.w);
        pl.x = pack_bf2(v.x - h.x, v.y - h.y);
        pl.y = pack_bf2(v.z - h.z, v.w - h.w);
        uint32_t off = sw128((uint32_t)(row * 128 + (q >> 1) * 16)) + (q & 1) * 8;
        *(uint2*)(dh + off) = ph;
        *(uint2*)(dl + off) = pl;
    }
}

// ---------------------------------------------------------------------------
// l[b,k] = sum_h W[k,h] * last_memory[b,h]
// ---------------------------------------------------------------------------
__global__ void __launch_bounds__(256) l_kernel(const float* __restrict__ lastm,
                                                const float* __restrict__ W) {
    __shared__ float lm[HH];
    __shared__ float Wt[32][HH + 1];
    const int b = blockIdx.x;
    const int tid = threadIdx.x;

    lm[tid] = lastm[b * HH + tid];
    __syncthreads();

    float acc = 0.0f;
    for (int h0 = 0; h0 < HH; h0 += 32) {
#pragma unroll
        for (int q = 0; q < 8; q++) {
            int f = tid + 256 * q;
            int k = f >> 3;
            int hq = f & 7;
            float4 v = *(const float4*)(W + k * HH + h0 + hq * 4);
            Wt[hq * 4 + 0][k] = v.x;
            Wt[hq * 4 + 1][k] = v.y;
            Wt[hq * 4 + 2][k] = v.z;
            Wt[hq * 4 + 3][k] = v.w;
        }
        __syncthreads();
#pragma unroll
        for (int hh = 0; hh < 32; hh++)
            acc = fmaf(Wt[hh][tid], lm[h0 + hh], acc);
        __syncthreads();
    }
    g_l[b * HH + tid] = acc;
}

// ---------------------------------------------------------------------------
// GEMM: A = X fp32 via direct LDG + in-register hi/lo split; B = U bf16 via
// 3-stage cp.async smem ring + ldmatrix. CTA 128x256, 16 warps (4m x 4n).
// Fused epilogue: scores = sum_n V[n]*tanh(acc + l[b,n]).
// ---------------------------------------------------------------------------
constexpr uint32_t STG = 65536;          // Uhi(nh0)|Uhi(nh1)|Ulo(nh0)|Ulo(nh1)
constexpr uint32_t GEMM_SMEM = 3 * STG;  // 192KB

__global__ void __launch_bounds__(512, 1) gemm_kernel(const float* __restrict__ X,
                                                      const float* __restrict__ Vv) {
    extern __shared__ __align__(1024) char smem[];
    __shared__ float vsm[256];
    __shared__ float s_red[4][128];

    const uint32_t sb = smem_u32(smem);
    const int tid = threadIdx.x;
    const int lane = tid & 31;
    const int wid = tid >> 5;
    const int wm = wid & 3;
    const int wn = wid >> 2;
    const int m = blockIdx.x;

    if (tid < 256) vsm[tid] = Vv[tid];

    float acc[2][8][4];
#pragma unroll
    for (int i = 0; i < 2; i++)
#pragma unroll
        for (int j = 0; j < 8; j++)
#pragma unroll
            for (int k = 0; k < 4; k++) acc[i][j][k] = 0.0f;

    // U stage loader: 4 regions x 16KB; thread covers 32B per region
    auto stage = [&](int kc, uint32_t sbase) {
        const char* s0 = (const char*)(g_Uhi + (size_t)(0 * 4 + kc) * BLK_ELEMS);
        const char* s1 = (const char*)(g_Uhi + (size_t)(1 * 4 + kc) * BLK_ELEMS);
        const char* s2 = (const char*)(g_Ulo + (size_t)(0 * 4 + kc) * BLK_ELEMS);
        const char* s3 = (const char*)(g_Ulo + (size_t)(1 * 4 + kc) * BLK_ELEMS);
        uint32_t o = (uint32_t)tid * 32u;
        uint32_t d = sbase + o;
        CPA16(d + 0u,          s0 + o); CPA16(d + 16u,         s0 + o + 16);
        CPA16(d + 16384u,      s1 + o); CPA16(d + 16400u,      s1 + o + 16);
        CPA16(d + 32768u,      s2 + o); CPA16(d + 32784u,      s2 + o + 16);
        CPA16(d + 49152u,      s3 + o); CPA16(d + 49168u,      s3 + o + 16);
        asm volatile("cp.async.commit_group;");
    };
    stage(0, sb);
    stage(1, sb + STG);
    stage(2, sb + 2 * STG);

    // A row pointers (fragment layout: rows r, r+8 per mt; cols (lane&3)*2 + ...)
    const int r0 = m * 128 + wm * 32 + (lane >> 2);
    const float* pa[2][2];
#pragma unroll
    for (int mt = 0; mt < 2; mt++)
#pragma unroll
        for (int h = 0; h < 2; h++)
            pa[mt][h] = X + (size_t)(r0 + mt * 16 + h * 8) * HH + (lane & 3) * 2;

    // B (ldmatrix) lane addressing within a 128x64 SW128 block
    const int brow0 = (wn & 1) * 64 + (lane & 7) + ((lane >> 4) << 3);
    const int bkb = ((lane >> 3) & 1) * 16;
    const uint32_t uhi_base = (uint32_t)(wn >> 1) * 16384u;

    for (int kc = 0; kc < KCH; kc++) {
        const uint32_t cur = sb + (uint32_t)(kc % 3) * STG;
        if (kc == 0)      asm volatile("cp.async.wait_group 2;");
        else if (kc == 1) asm volatile("cp.async.wait_group 1;");
        else if (kc == 2) asm volatile("cp.async.wait_group 1;");
        else              asm volatile("cp.async.wait_group 0;");
        __syncthreads();
        if (kc == 1) stage(3, sb);   // buf0 free: all threads passed compute(0)

#pragma unroll
        for (int k0 = 0; k0 < 4; k0++) {
            const int colb = kc * 64 + k0 * 16;
            const uint32_t kb = (uint32_t)k0 * 32u;

            // A fragments from gmem fp32, split hi/lo in registers
            uint32_t Ahi[2][4], Alo[2][4];
#pragma unroll
            for (int mt = 0; mt < 2; mt++) {
                float2 v00 = *(const float2*)(pa[mt][0] + colb);
                float2 v10 = *(const float2*)(pa[mt][1] + colb);
                float2 v01 = *(const float2*)(pa[mt][0] + colb + 8);
                float2 v11 = *(const float2*)(pa[mt][1] + colb + 8);
                cvt_hilo(v00, Ahi[mt][0], Alo[mt][0]);
                cvt_hilo(v10, Ahi[mt][1], Alo[mt][1]);
                cvt_hilo(v01, Ahi[mt][2], Alo[mt][2]);
                cvt_hilo(v11, Ahi[mt][3], Alo[mt][3]);
            }

#pragma unroll
            for (int ntp = 0; ntp < 4; ntp++) {
                uint32_t roff = (uint32_t)((brow0 + ntp * 16) * 128);
                uint32_t bh[4], bl[4];
                ldsm4(bh, cur + uhi_base + sw128(roff + kb + bkb));
                ldsm4(bl, cur + uhi_base + 32768u + sw128(roff + kb + bkb));
#pragma unroll
                for (int mt = 0; mt < 2; mt++) {
#pragma unroll
                    for (int sub = 0; sub < 2; sub++) {
                        float* c = acc[mt][ntp * 2 + sub];
                        mma_bf16(c, Ahi[mt], bh[sub * 2], bh[sub * 2 + 1]);
                        mma_bf16(c, Ahi[mt], bl[sub * 2], bl[sub * 2 + 1]);
                        mma_bf16(c, Alo[mt], bh[sub * 2], bh[sub * 2 + 1]);
                    }
                }
            }
        }
        __syncthreads();
    }

    // Epilogue: per row, sum_n V[n]*tanh(acc + l[b,n]); reduce quad -> warps
#pragma unroll
    for (int mt = 0; mt < 2; mt++) {
#pragma unroll
        for (int rh = 0; rh < 2; rh++) {
            int rowl = wm * 32 + mt * 16 + (lane >> 2) + rh * 8;
            int rowg = m * 128 + rowl;
            const float* lr = g_l + (rowg / SS) * HH;
            float s = 0.0f;
#pragma unroll
            for (int nt = 0; nt < 8; nt++) {
#pragma unroll
                for (int cl = 0; cl < 2; cl++) {
                    int col = wn * 64 + nt * 8 + (lane & 3) * 2 + cl;
                    float v = acc[mt][nt][rh * 2 + cl] + __ldg(lr + col);
                    s = fmaf(vsm[col], tanh_fma(v), s);
                }
            }
            s += __shfl_xor_sync(0xffffffffu, s, 1);
            s += __shfl_xor_sync(0xffffffffu, s, 2);
            if ((lane & 3) == 0) s_red[wn][rowl] = s;
        }
    }
    __syncthreads();
    if (tid < 128)
        g_sc[m * 128 + tid] = s_red[0][tid] + s_red[1][tid] + s_red[2][tid] + s_red[3][tid];
}

// ---------------------------------------------------------------------------
// softmax over S + pooled + final projection (4 accumulators)
// ---------------------------------------------------------------------------
__global__ void __launch_bounds__(256) pool_kernel(const float* __restrict__ X,
                                                   const float* __restrict__ MW,
                                                   const float* __restrict__ Mb,
                                                   float* __restrict__ out) {
    __shared__ float sal[SS];
    __shared__ float red[8];
    __shared__ float4 red4[8];

    const int b = blockIdx.x;
    const int tid = threadIdx.x;
    const int lane = tid & 31;
    const int w = tid >> 5;

    float v = (tid < SS) ? g_sc[b * SS + tid] : __int_as_float(0xff800000);
    float mx = v;
#pragma unroll
    for (int o = 16; o; o >>= 1) mx = fmaxf(mx, __shfl_xor_sync(0xffffffffu, mx, o));
    if (lane == 0) red[w] = mx;
    __syncthreads();
    float bm = red[0];
#pragma unroll
    for (int i = 1; i < 8; i++) bm = fmaxf(bm, red[i]);

    float e = (tid < SS) ? __expf(v - bm) : 0.0f;
    float s = e;
#pragma unroll
    for (int o = 16; o; o >>= 1) s += __shfl_xor_sync(0xffffffffu, s, o);
    __syncthreads();
    if (lane == 0) red[w] = s;
    __syncthreads();
    float bs = 0.0f;
#pragma unroll
    for (int i = 0; i < 8; i++) bs += red[i];

    if (tid < SS) sal[tid] = e / bs;
    __syncthreads();

    const float* Xb = X + (size_t)b * SS * HH + tid;
    float a0 = 0.0f, a1 = 0.0f, a2 = 0.0f, a3 = 0.0f;
#pragma unroll 4
    for (int sdx = 0; sdx < SS; sdx += 4) {
        a0 = fmaf(sal[sdx + 0], Xb[(size_t)(sdx + 0) * HH], a0);
        a1 = fmaf(sal[sdx + 1], Xb[(size_t)(sdx + 1) * HH], a1);
        a2 = fmaf(sal[sdx + 2], Xb[(size_t)(sdx + 2) * HH], a2);
        a3 = fmaf(sal[sdx + 3], Xb[(size_t)(sdx + 3) * HH], a3);
    }
    float acc = (a0 + a1) + (a2 + a3);

    float4 p;
    p.x = acc * MW[0 * HH + tid];
    p.y = acc * MW[1 * HH + tid];
    p.z = acc * MW[2 * HH + tid];
    p.w = acc * MW[3 * HH + tid];
#pragma unroll
    for (int o = 16; o; o >>= 1) {
        p.x += __shfl_xor_sync(0xffffffffu, p.x, o);
        p.y += __shfl_xor_sync(0xffffffffu, p.y, o);
        p.z += __shfl_xor_sync(0xffffffffu, p.z, o);
        p.w += __shfl_xor_sync(0xffffffffu, p.w, o);
    }
    if (lane == 0) red4[w] = p;
    __syncthreads();
    if (tid == 0) {
        float4 t = red4[0];
#pragma unroll
        for (int i = 1; i < 8; i++) {
            t.x += red4[i].x; t.y += red4[i].y; t.z += red4[i].z; t.w += red4[i].w;
        }
        out[b * 4 + 0] = t.x + Mb[0];
        out[b * 4 + 1] = t.y + Mb[1];
        out[b * 4 + 2] = t.z + Mb[2];
        out[b * 4 + 3] = t.w + Mb[3];
    }
}

// ---------------------------------------------------------------------------
extern "C" void kernel_launch(void* const* d_in, const int* in_sizes, int n_in,
                              void* d_out, int out_size) {
    const float* X     = (const float*)d_in[0];
    const float* lastm = (const float*)d_in[1];
    const float* U     = (const float*)d_in[2];
    const float* W     = (const float*)d_in[3];
    const float* Vv    = (const float*)d_in[4];
    const float* MW    = (const float*)d_in[5];
    const float* Mb    = (const float*)d_in[6];
    float* out = (float*)d_out;

    __nv_bfloat16 *uhi, *ulo;
    cudaGetSymbolAddress((void**)&uhi, g_Uhi);
    cudaGetSymbolAddress((void**)&ulo, g_Ulo);

    cudaFuncSetAttribute(gemm_kernel, cudaFuncAttributeMaxDynamicSharedMemorySize, GEMM_SMEM);

    conv_kernel<<<2 * KCH, 128>>>(U, uhi, ulo);
    l_kernel<<<BB, 256>>>(lastm, W);
    gemm_kernel<<<MTILES, 512, GEMM_SMEM>>>(X, Vv);
    pool_kernel<<<BB, 256>>>(X, MW, Mb, out);
}

// round 7
// speedup vs baseline: 1.1233x; 1.1233x over previous
#include <cuda_runtime.h>
#include <cuda_bf16.h>
#include <cstdint>

#define BB 512
#define SS 200
#define HH 256
#define MROWS (BB * SS)        // 102400 = 800 * 128
#define MTILES 800
#define KCH 4                  // K chunks of 64
#define BLK_ELEMS (128 * 64)   // one swizzled U block (bf16) = 16KB

// ---------------- scratch (no cudaMalloc allowed) ----------------
__device__ float g_l[BB * HH];
__device__ float g_sc[MROWS];
__device__ __align__(128) __nv_bfloat16 g_Uhi[2 * KCH * BLK_ELEMS];
__device__ __align__(128) __nv_bfloat16 g_Ulo[2 * KCH * BLK_ELEMS];

// ---------------- helpers ----------------
__device__ __forceinline__ uint32_t smem_u32(const void* p) {
    uint32_t a;
    asm("{ .reg .u64 t; cvta.to.shared.u64 t, %1; cvt.u32.u64 %0, t; }" : "=r"(a) : "l"(p));
    return a;
}
__device__ __forceinline__ uint32_t sw128(uint32_t o) { return o ^ ((o >> 3) & 0x70); }

__device__ __forceinline__ uint32_t pack_bf2(float x, float y) {
    uint32_t a = (uint32_t)__bfloat16_as_ushort(__float2bfloat16_rn(x));
    uint32_t b = (uint32_t)__bfloat16_as_ushort(__float2bfloat16_rn(y));
    return a | (b << 16);
}

// in-register split of a float2 into bf16 hi pair + bf16 lo pair
__device__ __forceinline__ void cvt_hilo(float2 v, uint32_t& hi, uint32_t& lo) {
    __nv_bfloat162 hb = __float22bfloat162_rn(v);
    hi = *(uint32_t*)&hb;
    float h0 = __int_as_float(hi << 16);
    float h1 = __int_as_float(hi & 0xffff0000u);
    float2 l;
    l.x = v.x - h0;
    l.y = v.y - h1;
    __nv_bfloat162 lb = __float22bfloat162_rn(l);
    lo = *(uint32_t*)&lb;
}

// MUFU-free tanh (FMA/ALU pipes only); |err| <= ~3.4e-5
__device__ __forceinline__ float tanh_fma(float x) {
    float t = fminf(fabsf(x), 5.5f) * 2.8853900817779268f;  // 2*log2(e)*|x|
    int n = __float2int_rn(t);
    float f = t - (float)n;
    float p = 1.5403530393381608e-4f;
    p = fmaf(p, f, 1.3333558146428443e-3f);
    p = fmaf(p, f, 9.6181291076284772e-3f);
    p = fmaf(p, f, 5.5504108664821580e-2f);
    p = fmaf(p, f, 2.4022650695910071e-1f);
    p = fmaf(p, f, 6.9314718055994531e-1f);
    p = fmaf(p, f, 1.0f);
    float E = __int_as_float(__float_as_int(p) + (n << 23)); // e^{2|x|}
    float D = E + 1.0f;
    float r = __int_as_float(0x7EF311C3 - __float_as_int(D));
    r = r * fmaf(-D, r, 2.0f);
    r = r * fmaf(-D, r, 2.0f);
    r = r * fmaf(-D, r, 2.0f);
    float y = fmaf(-2.0f, r, 1.0f);
    return copysignf(y, x);
}

__device__ __forceinline__ void ldsm4(uint32_t* r, uint32_t addr) {
    asm volatile("ldmatrix.sync.aligned.m8n8.x4.shared.b16 {%0,%1,%2,%3}, [%4];"
                 : "=r"(r[0]), "=r"(r[1]), "=r"(r[2]), "=r"(r[3]) : "r"(addr));
}
__device__ __forceinline__ void mma_bf16(float* c, const uint32_t* a, uint32_t b0, uint32_t b1) {
    asm volatile(
        "mma.sync.aligned.m16n8k16.row.col.f32.bf16.bf16.f32 "
        "{%0,%1,%2,%3}, {%4,%5,%6,%7}, {%8,%9}, {%0,%1,%2,%3};"
        : "+f"(c[0]), "+f"(c[1]), "+f"(c[2]), "+f"(c[3])
        : "r"(a[0]), "r"(a[1]), "r"(a[2]), "r"(a[3]), "r"(b0), "r"(b1));
}
#define CPA16(dst, src) \
    asm volatile("cp.async.cg.shared.global [%0], [%1], 16;" :: "r"(dst), "l"(src))

// ---------------------------------------------------------------------------
// conv (U only, 8 CTAs): fp32 -> bf16 (hi, lo) pre-swizzled SW128 128x64 blocks
// ---------------------------------------------------------------------------
__global__ void __launch_bounds__(128) conv_kernel(const float* __restrict__ S,
                                                   __nv_bfloat16* __restrict__ DH,
                                                   __nv_bfloat16* __restrict__ DL) {
    const int blk = blockIdx.x;
    const int mt = blk >> 2;
    const int c = blk & 3;
    const int tid = threadIdx.x;
    char* dh = (char*)(DH + (size_t)blk * BLK_ELEMS);
    char* dl = (char*)(DL + (size_t)blk * BLK_ELEMS);

#pragma unroll 4
    for (int it = 0; it < 16; it++) {
        int f = it * 128 + tid;
        int row = f >> 4;
        int q = f & 15;
        float4 v = *(const float4*)(S + ((size_t)(mt * 128 + row)) * HH + c * 64 + q * 4);
        float4 h;
        h.x = __bfloat162float(__float2bfloat16_rn(v.x));
        h.y = __bfloat162float(__float2bfloat16_rn(v.y));
        h.z = __bfloat162float(__float2bfloat16_rn(v.z));
        h.w = __bfloat162float(__float2bfloat16_rn(v.w));
        uint2 ph, pl;
        ph.x = pack_bf2(v.x, v.y);
        ph.y = pack_bf2(v.z, v.w);
        pl.x = pack_bf2(v.x - h.x, v.y - h.y);
        pl.y = pack_bf2(v.z - h.z, v.w - h.w);
        uint32_t off = sw128((uint32_t)(row * 128 + (q >> 1) * 16)) + (q & 1) * 8;
        *(uint2*)(dh + off) = ph;
        *(uint2*)(dl + off) = pl;
    }
}

// ---------------------------------------------------------------------------
// l[b,k] = sum_h W[k,h] * last_memory[b,h]
// ---------------------------------------------------------------------------
__global__ void __launch_bounds__(256) l_kernel(const float* __restrict__ lastm,
                                                const float* __restrict__ W) {
    __shared__ float lm[HH];
    __shared__ float Wt[32][HH + 1];
    const int b = blockIdx.x;
    const int tid = threadIdx.x;

    lm[tid] = lastm[b * HH + tid];
    __syncthreads();

    float acc = 0.0f;
    for (int h0 = 0; h0 < HH; h0 += 32) {
#pragma unroll
        for (int q = 0; q < 8; q++) {
            int f = tid + 256 * q;
            int k = f >> 3;
            int hq = f & 7;
            float4 v = *(const float4*)(W + k * HH + h0 + hq * 4);
            Wt[hq * 4 + 0][k] = v.x;
            Wt[hq * 4 + 1][k] = v.y;
            Wt[hq * 4 + 2][k] = v.z;
            Wt[hq * 4 + 3][k] = v.w;
        }
        __syncthreads();
#pragma unroll
        for (int hh = 0; hh < 32; hh++)
            acc = fmaf(Wt[hh][tid], lm[h0 + hh], acc);
        __syncthreads();
    }
    g_l[b * HH + tid] = acc;
}

// ---------------------------------------------------------------------------
// GEMM: A = X fp32 staged via cp.async smem (XOR-swizzled) + in-register
// hi/lo split; B = U bf16 via cp.async + ldmatrix. CTA 128x256, 16 warps.
// Fused epilogue: scores = sum_n V[n]*tanh(acc + l[b,n]).
// Stage = [X fp32 32KB][Uhi0][Uhi1][Ulo0][Ulo1] (16KB each) = 96KB, x2 stages.
// ---------------------------------------------------------------------------
constexpr uint32_t STG = 98304;          // 96KB
constexpr uint32_t GEMM_SMEM = 2 * STG;  // 192KB
constexpr uint32_t UOFF = 32768;         // U region base within stage

__global__ void __launch_bounds__(512, 1) gemm_kernel(const float* __restrict__ X,
                                                      const float* __restrict__ Vv) {
    extern __shared__ __align__(1024) char smem[];
    __shared__ float vsm[256];
    __shared__ float s_red[4][128];

    const uint32_t sb = smem_u32(smem);
    const int tid = threadIdx.x;
    const int lane = tid & 31;
    const int wid = tid >> 5;
    const int wm = wid & 3;
    const int wn = wid >> 2;
    const int m = blockIdx.x;

    if (tid < 256) vsm[tid] = Vv[tid];

    float acc[2][8][4];
#pragma unroll
    for (int i = 0; i < 2; i++)
#pragma unroll
        for (int j = 0; j < 8; j++)
#pragma unroll
            for (int k = 0; k < 4; k++) acc[i][j][k] = 0.0f;

    // stage loader: X tile (rows m*128.., cols kc*64..+64 fp32) + 4 U regions
    auto stage = [&](int kc, uint32_t sbase) {
        const char* xsrc = (const char*)(X + (size_t)m * 128 * HH + kc * 64);
#pragma unroll
        for (int i = 0; i < 4; i++) {
            int c = tid + 512 * i;           // 16B chunk id, 2048 total
            int row = c >> 4;
            int u = c & 15;
            uint32_t d = sbase + (uint32_t)(row * 256) +
                         (uint32_t)((u ^ ((row & 7) * 2)) << 4);
            CPA16(d, xsrc + (size_t)row * 1024 + u * 16);
        }
        const char* s0 = (const char*)(g_Uhi + (size_t)(0 * 4 + kc) * BLK_ELEMS);
        const char* s1 = (const char*)(g_Uhi + (size_t)(1 * 4 + kc) * BLK_ELEMS);
        const char* s2 = (const char*)(g_Ulo + (size_t)(0 * 4 + kc) * BLK_ELEMS);
        const char* s3 = (const char*)(g_Ulo + (size_t)(1 * 4 + kc) * BLK_ELEMS);
        uint32_t o = (uint32_t)tid * 32u;
        uint32_t d = sbase + UOFF + o;
        CPA16(d + 0u,     s0 + o); CPA16(d + 16u,    s0 + o + 16);
        CPA16(d + 16384u, s1 + o); CPA16(d + 16400u, s1 + o + 16);
        CPA16(d + 32768u, s2 + o); CPA16(d + 32784u, s2 + o + 16);
        CPA16(d + 49152u, s3 + o); CPA16(d + 49168u, s3 + o + 16);
        asm volatile("cp.async.commit_group;");
    };
    stage(0, sb);

    // A fragment addressing (local row within 128-row tile)
    const int rbase = wm * 32 + (lane >> 2);             // + mt*16 + h*8
    const uint32_t aswz = (uint32_t)(((lane >> 2) & 7) * 2);
    const uint32_t au0 = (uint32_t)((lane & 3) >> 1);    // + k0*4 (+2 for hi half)
    const uint32_t ain8 = (uint32_t)((lane & 1) * 8);

    // B (ldmatrix) lane addressing within a 128x64 SW128 block
    const int brow0 = (wn & 1) * 64 + (lane & 7) + ((lane >> 4) << 3);
    const int bkb = ((lane >> 3) & 1) * 16;
    const uint32_t uhi_base = UOFF + (uint32_t)(wn >> 1) * 16384u;

    for (int kc = 0; kc < KCH; kc++) {
        const uint32_t cur = sb + (uint32_t)(kc & 1) * STG;
        if (kc + 1 < KCH) {
            stage(kc + 1, sb + (uint32_t)((kc + 1) & 1) * STG);
            asm volatile("cp.async.wait_group 1;");
        } else {
            asm volatile("cp.async.wait_group 0;");
        }
        __syncthreads();

#pragma unroll
        for (int k0 = 0; k0 < 4; k0++) {
            const uint32_t kb = (uint32_t)k0 * 32u;
            const uint32_t ub0 = (uint32_t)(k0 * 4) + au0;

            // A fragments: LDS.64 fp32 pairs, split hi/lo in registers
            uint32_t Ahi[2][4], Alo[2][4];
#pragma unroll
            for (int mt = 0; mt < 2; mt++) {
                const uint32_t r0off = cur + (uint32_t)((rbase + mt * 16) * 256);
                const uint32_t r1off = r0off + 8 * 256;
                float2 v00 = *(const float2*)(smem + (r0off - sb) + (((ub0 ^ aswz) << 4) + ain8));
                float2 v10 = *(const float2*)(smem + (r1off - sb) + (((ub0 ^ aswz) << 4) + ain8));
                float2 v01 = *(const float2*)(smem + (r0off - sb) + ((((ub0 + 2) ^ aswz) << 4) + ain8));
                float2 v11 = *(const float2*)(smem + (r1off - sb) + ((((ub0 + 2) ^ aswz) << 4) + ain8));
                cvt_hilo(v00, Ahi[mt][0], Alo[mt][0]);
                cvt_hilo(v10, Ahi[mt][1], Alo[mt][1]);
                cvt_hilo(v01, Ahi[mt][2], Alo[mt][2]);
                cvt_hilo(v11, Ahi[mt][3], Alo[mt][3]);
            }

#pragma unroll
            for (int ntp = 0; ntp < 4; ntp++) {
                uint32_t roff = (uint32_t)((brow0 + ntp * 16) * 128);
                uint32_t bh[4], bl[4];
                ldsm4(bh, cur + uhi_base + sw128(roff + kb + bkb));
                ldsm4(bl, cur + uhi_base + 32768u + sw128(roff + kb + bkb));
#pragma unroll
                for (int mt = 0; mt < 2; mt++) {
#pragma unroll
                    for (int sub = 0; sub < 2; sub++) {
                        float* c = acc[mt][ntp * 2 + sub];
                        mma_bf16(c, Ahi[mt], bh[sub * 2], bh[sub * 2 + 1]);
                        mma_bf16(c, Ahi[mt], bl[sub * 2], bl[sub * 2 + 1]);
                        mma_bf16(c, Alo[mt], bh[sub * 2], bh[sub * 2 + 1]);
                    }
                }
            }
        }
        __syncthreads();
    }

    // Epilogue: per row, sum_n V[n]*tanh(acc + l[b,n]); reduce quad -> warps
#pragma unroll
    for (int mt = 0; mt < 2; mt++) {
#pragma unroll
        for (int rh = 0; rh < 2; rh++) {
            int rowl = wm * 32 + mt * 16 + (lane >> 2) + rh * 8;
            int rowg = m * 128 + rowl;
            const float* lr = g_l + (rowg / SS) * HH;
            float s = 0.0f;
#pragma unroll
            for (int nt = 0; nt < 8; nt++) {
#pragma unroll
                for (int cl = 0; cl < 2; cl++) {
                    int col = wn * 64 + nt * 8 + (lane & 3) * 2 + cl;
                    float v = acc[mt][nt][rh * 2 + cl] + __ldg(lr + col);
                    s = fmaf(vsm[col], tanh_fma(v), s);
                }
            }
            s += __shfl_xor_sync(0xffffffffu, s, 1);
            s += __shfl_xor_sync(0xffffffffu, s, 2);
            if ((lane & 3) == 0) s_red[wn][rowl] = s;
        }
    }
    __syncthreads();
    if (tid < 128)
        g_sc[m * 128 + tid] = s_red[0][tid] + s_red[1][tid] + s_red[2][tid] + s_red[3][tid];
}

// ---------------------------------------------------------------------------
// softmax over S + pooled + final projection (R3-proven version)
// ---------------------------------------------------------------------------
__global__ void __launch_bounds__(256) pool_kernel(const float* __restrict__ X,
                                                   const float* __restrict__ MW,
                                                   const float* __restrict__ Mb,
                                                   float* __restrict__ out) {
    __shared__ float sal[SS];
    __shared__ float red[8];
    __shared__ float4 red4[8];

    const int b = blockIdx.x;
    const int tid = threadIdx.x;
    const int lane = tid & 31;
    const int w = tid >> 5;

    float v = (tid < SS) ? g_sc[b * SS + tid] : __int_as_float(0xff800000);
    float mx = v;
#pragma unroll
    for (int o = 16; o; o >>= 1) mx = fmaxf(mx, __shfl_xor_sync(0xffffffffu, mx, o));
    if (lane == 0) red[w] = mx;
    __syncthreads();
    float bm = red[0];
#pragma unroll
    for (int i = 1; i < 8; i++) bm = fmaxf(bm, red[i]);

    float e = (tid < SS) ? __expf(v - bm) : 0.0f;
    float s = e;
#pragma unroll
    for (int o = 16; o; o >>= 1) s += __shfl_xor_sync(0xffffffffu, s, o);
    __syncthreads();
    if (lane == 0) red[w] = s;
    __syncthreads();
    float bs = 0.0f;
#pragma unroll
    for (int i = 0; i < 8; i++) bs += red[i];

    if (tid < SS) sal[tid] = e / bs;
    __syncthreads();

    const float* Xb = X + (size_t)b * SS * HH + tid;
    float acc = 0.0f;
#pragma unroll 8
    for (int sdx = 0; sdx < SS; sdx++)
        acc = fmaf(sal[sdx], Xb[(size_t)sdx * HH], acc);

    float4 p;
    p.x = acc * MW[0 * HH + tid];
    p.y = acc * MW[1 * HH + tid];
    p.z = acc * MW[2 * HH + tid];
    p.w = acc * MW[3 * HH + tid];
#pragma unroll
    for (int o = 16; o; o >>= 1) {
        p.x += __shfl_xor_sync(0xffffffffu, p.x, o);
        p.y += __shfl_xor_sync(0xffffffffu, p.y, o);
        p.z += __shfl_xor_sync(0xffffffffu, p.z, o);
        p.w += __shfl_xor_sync(0xffffffffu, p.w, o);
    }
    if (lane == 0) red4[w] = p;
    __syncthreads();
    if (tid == 0) {
        float4 t = red4[0];
#pragma unroll
        for (int i = 1; i < 8; i++) {
            t.x += red4[i].x; t.y += red4[i].y; t.z += red4[i].z; t.w += red4[i].w;
        }
        out[b * 4 + 0] = t.x + Mb[0];
        out[b * 4 + 1] = t.y + Mb[1];
        out[b * 4 + 2] = t.z + Mb[2];
        out[b * 4 + 3] = t.w + Mb[3];
    }
}

// ---------------------------------------------------------------------------
extern "C" void kernel_launch(void* const* d_in, const int* in_sizes, int n_in,
                              void* d_out, int out_size) {
    const float* X     = (const float*)d_in[0];
    const float* lastm = (const float*)d_in[1];
    const float* U     = (const float*)d_in[2];
    const float* W     = (const float*)d_in[3];
    const float* Vv    = (const float*)d_in[4];
    const float* MW    = (const float*)d_in[5];
    const float* Mb    = (const float*)d_in[6];
    float* out = (float*)d_out;

    __nv_bfloat16 *uhi, *ulo;
    cudaGetSymbolAddress((void**)&uhi, g_Uhi);
    cudaGetSymbolAddress((void**)&ulo, g_Ulo);

    cudaFuncSetAttribute(gemm_kernel, cudaFuncAttributeMaxDynamicSharedMemorySize, GEMM_SMEM);

    conv_kernel<<<2 * KCH, 128>>>(U, uhi, ulo);
    l_kernel<<<BB, 256>>>(lastm, W);
    gemm_kernel<<<MTILES, 512, GEMM_SMEM>>>(X, Vv);
    pool_kernel<<<BB, 256>>>(X, MW, Mb, out);
}

// round 9
// speedup vs baseline: 1.4460x; 1.2873x over previous
#include <cuda_runtime.h>
#include <cuda_bf16.h>
#include <cstdint>

#define BB 512
#define SS 200
#define HH 256
#define MROWS (BB * SS)        // 102400 = 800 * 128
#define MTILES 800
#define NCH 8                  // K chunks of 32
#define CHUNK_BYTES 16384      // per chunk: hi 8KB | lo 8KB (tiled128 format)

// ---------------- scratch (no cudaMalloc allowed) ----------------
__device__ float g_l[BB * HH];
__device__ float g_sc[2 * MROWS];  // partial scores per n-half
__device__ __align__(128) char g_Xc[(size_t)MTILES * NCH * CHUNK_BYTES];  // 100MB
__device__ __align__(128) char g_Uc[2 * NCH * CHUNK_BYTES];               // 256KB

// ---------------- helpers ----------------
__device__ __forceinline__ uint32_t smem_u32(const void* p) {
    uint32_t a;
    asm("{ .reg .u64 t; cvta.to.shared.u64 t, %1; cvt.u32.u64 %0, t; }" : "=r"(a) : "l"(p));
    return a;
}
__device__ __forceinline__ uint32_t pack_bf2(float x, float y) {
    uint32_t a = (uint32_t)__bfloat16_as_ushort(__float2bfloat16_rn(x));
    uint32_t b = (uint32_t)__bfloat16_as_ushort(__float2bfloat16_rn(y));
    return a | (b << 16);
}

// MUFU-free tanh (FMA/ALU pipes only); |err| <= ~3.4e-5
__device__ __forceinline__ float tanh_fma(float x) {
    float t = fminf(fabsf(x), 5.5f) * 2.8853900817779268f;  // 2*log2(e)*|x|
    int n = __float2int_rn(t);
    float f = t - (float)n;
    float p = 1.5403530393381608e-4f;
    p = fmaf(p, f, 1.3333558146428443e-3f);
    p = fmaf(p, f, 9.6181291076284772e-3f);
    p = fmaf(p, f, 5.5504108664821580e-2f);
    p = fmaf(p, f, 2.4022650695910071e-1f);
    p = fmaf(p, f, 6.9314718055994531e-1f);
    p = fmaf(p, f, 1.0f);
    float E = __int_as_float(__float_as_int(p) + (n << 23)); // e^{2|x|}
    float D = E + 1.0f;
    float r = __int_as_float(0x7EF311C3 - __float_as_int(D));
    r = r * fmaf(-D, r, 2.0f);
    r = r * fmaf(-D, r, 2.0f);
    r = r * fmaf(-D, r, 2.0f);
    float y = fmaf(-2.0f, r, 1.0f);
    return copysignf(y, x);
}

__device__ __forceinline__ void ldsm4(uint32_t* r, uint32_t addr) {
    asm volatile("ldmatrix.sync.aligned.m8n8.x4.shared.b16 {%0,%1,%2,%3}, [%4];"
                 : "=r"(r[0]), "=r"(r[1]), "=r"(r[2]), "=r"(r[3]) : "r"(addr));
}
__device__ __forceinline__ void mma_bf16(float* c, const uint32_t* a, uint32_t b0, uint32_t b1) {
    asm volatile(
        "mma.sync.aligned.m16n8k16.row.col.f32.bf16.bf16.f32 "
        "{%0,%1,%2,%3}, {%4,%5,%6,%7}, {%8,%9}, {%0,%1,%2,%3};"
        : "+f"(c[0]), "+f"(c[1]), "+f"(c[2]), "+f"(c[3])
        : "r"(a[0]), "r"(a[1]), "r"(a[2]), "r"(a[3]), "r"(b0), "r"(b1));
}
#define CPA16(dst, src) \
    asm volatile("cp.async.cg.shared.global [%0], [%1], 16;" :: "r"(dst), "l"(src))

// ---------------------------------------------------------------------------
// conv: fp32 rows -> tiled128 bf16 hi/lo chunks.
// Chunk = 128 rows x 32 k. Tile (rg, kg) = 8 rows x 8 k, 128B contiguous at
// offset (rg*4 + kg)*128. Layout: [mt][kc][hi 8KB | lo 8KB].
// blockIdx = mt*8 + kc, 128 threads (thread = row).
// ---------------------------------------------------------------------------
__global__ void __launch_bounds__(128) conv_kernel(const float* __restrict__ S,
                                                   char* __restrict__ D) {
    const int blk = blockIdx.x;
    const int mt = blk >> 3;
    const int kc = blk & 7;
    const int r = threadIdx.x;

    const float* src = S + (size_t)(mt * 128 + r) * HH + kc * 32;
    char* dst = D + (size_t)blk * CHUNK_BYTES;
    const uint32_t rowbase = (uint32_t)((r >> 3) * 4 * 128 + (r & 7) * 16);

#pragma unroll
    for (int q = 0; q < 8; q++) {
        float4 v = *(const float4*)(src + q * 4);
        float4 h;
        h.x = __bfloat162float(__float2bfloat16_rn(v.x));
        h.y = __bfloat162float(__float2bfloat16_rn(v.y));
        h.z = __bfloat162float(__float2bfloat16_rn(v.z));
        h.w = __bfloat162float(__float2bfloat16_rn(v.w));
        uint2 ph, pl;
        ph.x = pack_bf2(v.x, v.y);
        ph.y = pack_bf2(v.z, v.w);
        pl.x = pack_bf2(v.x - h.x, v.y - h.y);
        pl.y = pack_bf2(v.z - h.z, v.w - h.w);
        uint32_t off = rowbase + (uint32_t)((q >> 1) * 128 + (q & 1) * 8);
        *(uint2*)(dst + off) = ph;
        *(uint2*)(dst + 8192 + off) = pl;
    }
}

// ---------------------------------------------------------------------------
// l[b,k] = sum_h W[k,h] * last_memory[b,h]
// ---------------------------------------------------------------------------
__global__ void __launch_bounds__(256) l_kernel(const float* __restrict__ lastm,
                                                const float* __restrict__ W) {
    __shared__ float lm[HH];
    __shared__ float Wt[32][HH + 1];
    const int b = blockIdx.x;
    const int tid = threadIdx.x;

    lm[tid] = lastm[b * HH + tid];
    __syncthreads();

    float acc = 0.0f;
    for (int h0 = 0; h0 < HH; h0 += 32) {
#pragma unroll
        for (int q = 0; q < 8; q++) {
            int f = tid + 256 * q;
            int k = f >> 3;
            int hq = f & 7;
            float4 v = *(const float4*)(W + k * HH + h0 + hq * 4);
            Wt[hq * 4 + 0][k] = v.x;
            Wt[hq * 4 + 1][k] = v.y;
            Wt[hq * 4 + 2][k] = v.z;
            Wt[hq * 4 + 3][k] = v.w;
        }
        __syncthreads();
#pragma unroll
        for (int hh = 0; hh < 32; hh++)
            acc = fmaf(Wt[hh][tid], lm[h0 + hh], acc);
        __syncthreads();
    }
    g_l[b * HH + tid] = acc;
}

// ---------------------------------------------------------------------------
// GEMM: CTA = 128 rows x 128 cols (nh half), 256 thr = 8 warps (4m x 2n).
// bf16 split-3 mma.sync; 3-stage cp.async ring over 8 K-chunks of 32,
// ONE __syncthreads per chunk. Stage = [Xhi|Xlo|Uhi|Ulo] 4x8KB = 32KB.
// Fused epilogue: partial scores = sum_n V[n]*tanh(acc + l[b,n]).
// ---------------------------------------------------------------------------
constexpr uint32_t STG = 32768;
constexpr uint32_t GEMM_SMEM = 3 * STG;  // 96KB -> 2 CTAs/SM

__global__ void __launch_bounds__(256, 2) gemm_kernel(const float* __restrict__ Vv) {
    extern __shared__ __align__(1024) char smem[];
    __shared__ float vsm[128];
    __shared__ float s_red[2][128];

    const uint32_t sb = smem_u32(smem);
    const int tid = threadIdx.x;
    const int lane = tid & 31;
    const int wid = tid >> 5;
    const int wm = wid & 3;       // 4 m-warps x 32 rows
    const int wn = wid >> 2;      // 2 n-warps x 64 cols
    const int m = blockIdx.x;
    const int nh = blockIdx.y;

    if (tid < 128) vsm[tid] = Vv[nh * 128 + tid];

    float acc[2][8][4];
#pragma unroll
    for (int i = 0; i < 2; i++)
#pragma unroll
        for (int j = 0; j < 8; j++)
#pragma unroll
            for (int k = 0; k < 4; k++) acc[i][j][k] = 0.0f;

    // stage loader: contiguous 16KB X chunk + 16KB U chunk
    auto stage = [&](int kc, uint32_t sbase) {
        const char* xs = g_Xc + ((size_t)m * NCH + kc) * CHUNK_BYTES;
        const char* us = g_Uc + ((size_t)nh * NCH + kc) * CHUNK_BYTES;
        uint32_t o = (uint32_t)tid * 64u;
        uint32_t d = sbase + o;
        CPA16(d + 0u,  xs + o);      CPA16(d + 16u, xs + o + 16);
        CPA16(d + 32u, xs + o + 32); CPA16(d + 48u, xs + o + 48);
        uint32_t d2 = sbase + 16384u + o;
        CPA16(d2 + 0u,  us + o);      CPA16(d2 + 16u, us + o + 16);
        CPA16(d2 + 32u, us + o + 32); CPA16(d2 + 48u, us + o + 48);
        asm volatile("cp.async.commit_group;");
    };
    stage(0, sb);
    stage(1, sb + STG);

    // ldmatrix lane addressing (tiled128): addr = base + tileidx*128 + (lane&7)*16
    const uint32_t lb = (uint32_t)((lane & 7) * 16);
    const uint32_t ab1 = (uint32_t)((lane >> 3) & 1);  // A: row-group select
    const uint32_t ab2 = (uint32_t)(lane >> 4);        // A: k-group select

    for (int kc = 0; kc < NCH; kc++) {
        if (kc < NCH - 1) asm volatile("cp.async.wait_group 1;");
        else              asm volatile("cp.async.wait_group 0;");
        __syncthreads();
        if (kc + 2 < NCH) stage(kc + 2, sb + (uint32_t)((kc + 2) % 3) * STG);

        const uint32_t cur = sb + (uint32_t)(kc % 3) * STG;

#pragma unroll
        for (int k0 = 0; k0 < 2; k0++) {
            const uint32_t kg = (uint32_t)(k0 * 2);

            // A fragments (rows wm*32 + mt*16 .. +16), hi & lo
            uint32_t Ahi[2][4], Alo[2][4];
#pragma unroll
            for (int mt = 0; mt < 2; mt++) {
                uint32_t tix = ((uint32_t)(wm * 4 + mt * 2) + ab1) * 4 + kg + ab2;
                uint32_t addr = cur + tix * 128u + lb;
                ldsm4(Ahi[mt], addr);
                ldsm4(Alo[mt], addr + 8192u);
            }

#pragma unroll
            for (int ntp = 0; ntp < 4; ntp++) {
                // B tiles (n-rows wn*64 + ntp*16 .. +16)
                uint32_t tix = ((uint32_t)(wn * 8 + ntp * 2) + ab2) * 4 + kg + ab1;
                uint32_t addr = cur + 16384u + tix * 128u + lb;
                uint32_t bh[4], bl[4];
                ldsm4(bh, addr);
                ldsm4(bl, addr + 8192u);
#pragma unroll
                for (int mt = 0; mt < 2; mt++) {
#pragma unroll
                    for (int sub = 0; sub < 2; sub++) {
                        float* c = acc[mt][ntp * 2 + sub];
                        mma_bf16(c, Ahi[mt], bh[sub * 2], bh[sub * 2 + 1]);
                        mma_bf16(c, Ahi[mt], bl[sub * 2], bl[sub * 2 + 1]);
                        mma_bf16(c, Alo[mt], bh[sub * 2], bh[sub * 2 + 1]);
                    }
                }
            }
        }
    }

    // Epilogue: per row, sum over this CTA's 128 cols of V[n]*tanh(acc+l)
#pragma unroll
    for (int mt = 0; mt < 2; mt++) {
#pragma unroll
        for (int rh = 0; rh < 2; rh++) {
            int rowl = wm * 32 + mt * 16 + (lane >> 2) + rh * 8;
            int rowg = m * 128 + rowl;
            const float* lr = g_l + (rowg / SS) * HH + nh * 128;
            float s = 0.0f;
#pragma unroll
            for (int nt = 0; nt < 8; nt++) {
#pragma unroll
                for (int cl = 0; cl < 2; cl++) {
                    int col = wn * 64 + nt * 8 + (lane & 3) * 2 + cl;
                    float v = acc[mt][nt][rh * 2 + cl] + __ldg(lr + col);
                    s = fmaf(vsm[col], tanh_fma(v), s);
                }
            }
            s += __shfl_xor_sync(0xffffffffu, s, 1);
            s += __shfl_xor_sync(0xffffffffu, s, 2);
            if ((lane & 3) == 0) s_red[wn][rowl] = s;
        }
    }
    __syncthreads();
    if (tid < 128)
        g_sc[nh * MROWS + m * 128 + tid] = s_red[0][tid] + s_red[1][tid];
}

// ---------------------------------------------------------------------------
// softmax over S + pooled + final projection
// ---------------------------------------------------------------------------
__global__ void __launch_bounds__(256) pool_kernel(const float* __restrict__ X,
                                                   const float* __restrict__ MW,
                                                   const float* __restrict__ Mb,
                                                   float* __restrict__ out) {
    __shared__ float sal[SS];
    __shared__ float red[8];
    __shared__ float4 red4[8];

    const int b = blockIdx.x;
    const int tid = threadIdx.x;
    const int lane = tid & 31;
    const int w = tid >> 5;

    float v;
    if (tid < SS) {
        int idx = b * SS + tid;
        v = g_sc[idx] + g_sc[MROWS + idx];
    } else {
        v = __int_as_float(0xff800000);
    }
    float mx = v;
#pragma unroll
    for (int o = 16; o; o >>= 1) mx = fmaxf(mx, __shfl_xor_sync(0xffffffffu, mx, o));
    if (lane == 0) red[w] = mx;
    __syncthreads();
    float bm = red[0];
#pragma unroll
    for (int i = 1; i < 8; i++) bm = fmaxf(bm, red[i]);

    float e = (tid < SS) ? __expf(v - bm) : 0.0f;
    float s = e;
#pragma unroll
    for (int o = 16; o; o >>= 1) s += __shfl_xor_sync(0xffffffffu, s, o);
    __syncthreads();
    if (lane == 0) red[w] = s;
    __syncthreads();
    float bs = 0.0f;
#pragma unroll
    for (int i = 0; i < 8; i++) bs += red[i];

    if (tid < SS) sal[tid] = e / bs;
    __syncthreads();

    const float* Xb = X + (size_t)b * SS * HH + tid;
    float acc = 0.0f;
#pragma unroll 8
    for (int sdx = 0; sdx < SS; sdx++)
        acc = fmaf(sal[sdx], Xb[(size_t)sdx * HH], acc);

    float4 p;
    p.x = acc * MW[0 * HH + tid];
    p.y = acc * MW[1 * HH + tid];
    p.z = acc * MW[2 * HH + tid];
    p.w = acc * MW[3 * HH + tid];
#pragma unroll
    for (int o = 16; o; o >>= 1) {
        p.x += __shfl_xor_sync(0xffffffffu, p.x, o);
        p.y += __shfl_xor_sync(0xffffffffu, p.y, o);
        p.z += __shfl_xor_sync(0xffffffffu, p.z, o);
        p.w += __shfl_xor_sync(0xffffffffu, p.w, o);
    }
    if (lane == 0) red4[w] = p;
    __syncthreads();
    if (tid == 0) {
        float4 t = red4[0];
#pragma unroll
        for (int i = 1; i < 8; i++) {
            t.x += red4[i].x; t.y += red4[i].y; t.z += red4[i].z; t.w += red4[i].w;
        }
        out[b * 4 + 0] = t.x + Mb[0];
        out[b * 4 + 1] = t.y + Mb[1];
        out[b * 4 + 2] = t.z + Mb[2];
        out[b * 4 + 3] = t.w + Mb[3];
    }
}

// ---------------------------------------------------------------------------
extern "C" void kernel_launch(void* const* d_in, const int* in_sizes, int n_in,
                              void* d_out, int out_size) {
    const float* X     = (const float*)d_in[0];
    const float* lastm = (const float*)d_in[1];
    const float* U     = (const float*)d_in[2];
    const float* W     = (const float*)d_in[3];
    const float* Vv    = (const float*)d_in[4];
    const float* MW    = (const float*)d_in[5];
    const float* Mb    = (const float*)d_in[6];
    float* out = (float*)d_out;

    char *xc, *uc;
    cudaGetSymbolAddress((void**)&xc, g_Xc);
    cudaGetSymbolAddress((void**)&uc, g_Uc);

    cudaFuncSetAttribute(gemm_kernel, cudaFuncAttributeMaxDynamicSharedMemorySize, GEMM_SMEM);

    conv_kernel<<<2 * NCH, 128>>>(U, uc);          // U -> tiled128 (2 n-halves)
    conv_kernel<<<MTILES * NCH, 128>>>(X, xc);     // X -> tiled128
    l_kernel<<<BB, 256>>>(lastm, W);
    gemm_kernel<<<dim3(MTILES, 2), 256, GEMM_SMEM>>>(Vv);
    pool_kernel<<<BB, 256>>>(X, MW, Mb, out);
}

// round 10
// speedup vs baseline: 1.5818x; 1.0939x over previous
#include <cuda_runtime.h>
#include <cuda_bf16.h>
#include <cstdint>

#define BB 512
#define SS 200
#define HH 256
#define MROWS (BB * SS)        // 102400 = 1600 * 64
#define MT64 1600
#define NCH 8                  // K chunks of 32
#define CHUNK_BYTES 16384      // conv chunk: hi 8KB | lo 8KB (tiled128)

// ---------------- scratch (no cudaMalloc allowed) ----------------
__device__ float g_l[BB * HH];
__device__ float g_sc[2 * MROWS];  // partial scores per n-half
__device__ __align__(128) char g_Xc[(size_t)(MT64 / 2) * NCH * CHUNK_BYTES];  // 100MB
__device__ __align__(128) char g_Uc[2 * NCH * CHUNK_BYTES];                   // 256KB

// ---------------- helpers ----------------
__device__ __forceinline__ uint32_t smem_u32(const void* p) {
    uint32_t a;
    asm("{ .reg .u64 t; cvta.to.shared.u64 t, %1; cvt.u32.u64 %0, t; }" : "=r"(a) : "l"(p));
    return a;
}
__device__ __forceinline__ uint32_t pack_bf2(float x, float y) {
    uint32_t a = (uint32_t)__bfloat16_as_ushort(__float2bfloat16_rn(x));
    uint32_t b = (uint32_t)__bfloat16_as_ushort(__float2bfloat16_rn(y));
    return a | (b << 16);
}

// MUFU-free tanh (FMA/ALU pipes only); |err| <= ~3.4e-5
__device__ __forceinline__ float tanh_fma(float x) {
    float t = fminf(fabsf(x), 5.5f) * 2.8853900817779268f;  // 2*log2(e)*|x|
    int n = __float2int_rn(t);
    float f = t - (float)n;
    float p = 1.5403530393381608e-4f;
    p = fmaf(p, f, 1.3333558146428443e-3f);
    p = fmaf(p, f, 9.6181291076284772e-3f);
    p = fmaf(p, f, 5.5504108664821580e-2f);
    p = fmaf(p, f, 2.4022650695910071e-1f);
    p = fmaf(p, f, 6.9314718055994531e-1f);
    p = fmaf(p, f, 1.0f);
    float E = __int_as_float(__float_as_int(p) + (n << 23)); // e^{2|x|}
    float D = E + 1.0f;
    float r = __int_as_float(0x7EF311C3 - __float_as_int(D));
    r = r * fmaf(-D, r, 2.0f);
    r = r * fmaf(-D, r, 2.0f);
    r = r * fmaf(-D, r, 2.0f);
    float y = fmaf(-2.0f, r, 1.0f);
    return copysignf(y, x);
}

__device__ __forceinline__ void ldsm4(uint32_t* r, uint32_t addr) {
    asm volatile("ldmatrix.sync.aligned.m8n8.x4.shared.b16 {%0,%1,%2,%3}, [%4];"
                 : "=r"(r[0]), "=r"(r[1]), "=r"(r[2]), "=r"(r[3]) : "r"(addr));
}
__device__ __forceinline__ void mma_bf16(float* c, const uint32_t* a, uint32_t b0, uint32_t b1) {
    asm volatile(
        "mma.sync.aligned.m16n8k16.row.col.f32.bf16.bf16.f32 "
        "{%0,%1,%2,%3}, {%4,%5,%6,%7}, {%8,%9}, {%0,%1,%2,%3};"
        : "+f"(c[0]), "+f"(c[1]), "+f"(c[2]), "+f"(c[3])
        : "r"(a[0]), "r"(a[1]), "r"(a[2]), "r"(a[3]), "r"(b0), "r"(b1));
}
#define CPA16(dst, src) \
    asm volatile("cp.async.cg.shared.global [%0], [%1], 16;" :: "r"(dst), "l"(src))

// ---------------------------------------------------------------------------
// conv: fp32 rows -> tiled128 bf16 hi/lo chunks (unchanged, R9-proven).
// Chunk = 128 rows x 32 k. Tile (rg, kg) = 8 rows x 8 k, 128B at (rg*4+kg)*128.
// Layout: [mt128][kc][hi 8KB | lo 8KB]. blockIdx = mt*8 + kc, thread = row.
// ---------------------------------------------------------------------------
__global__ void __launch_bounds__(128) conv_kernel(const float* __restrict__ S,
                                                   char* __restrict__ D) {
    const int blk = blockIdx.x;
    const int mt = blk >> 3;
    const int kc = blk & 7;
    const int r = threadIdx.x;

    const float* src = S + (size_t)(mt * 128 + r) * HH + kc * 32;
    char* dst = D + (size_t)blk * CHUNK_BYTES;
    const uint32_t rowbase = (uint32_t)((r >> 3) * 4 * 128 + (r & 7) * 16);

#pragma unroll
    for (int q = 0; q < 8; q++) {
        float4 v = *(const float4*)(src + q * 4);
        float4 h;
        h.x = __bfloat162float(__float2bfloat16_rn(v.x));
        h.y = __bfloat162float(__float2bfloat16_rn(v.y));
        h.z = __bfloat162float(__float2bfloat16_rn(v.z));
        h.w = __bfloat162float(__float2bfloat16_rn(v.w));
        uint2 ph, pl;
        ph.x = pack_bf2(v.x, v.y);
        ph.y = pack_bf2(v.z, v.w);
        pl.x = pack_bf2(v.x - h.x, v.y - h.y);
        pl.y = pack_bf2(v.z - h.z, v.w - h.w);
        uint32_t off = rowbase + (uint32_t)((q >> 1) * 128 + (q & 1) * 8);
        *(uint2*)(dst + off) = ph;
        *(uint2*)(dst + 8192 + off) = pl;
    }
}

// ---------------------------------------------------------------------------
// l[b,k] = sum_h W[k,h] * last_memory[b,h]
// ---------------------------------------------------------------------------
__global__ void __launch_bounds__(256) l_kernel(const float* __restrict__ lastm,
                                                const float* __restrict__ W) {
    __shared__ float lm[HH];
    __shared__ float Wt[32][HH + 1];
    const int b = blockIdx.x;
    const int tid = threadIdx.x;

    lm[tid] = lastm[b * HH + tid];
    __syncthreads();

    float acc = 0.0f;
    for (int h0 = 0; h0 < HH; h0 += 32) {
#pragma unroll
        for (int q = 0; q < 8; q++) {
            int f = tid + 256 * q;
            int k = f >> 3;
            int hq = f & 7;
            float4 v = *(const float4*)(W + k * HH + h0 + hq * 4);
            Wt[hq * 4 + 0][k] = v.x;
            Wt[hq * 4 + 1][k] = v.y;
            Wt[hq * 4 + 2][k] = v.z;
            Wt[hq * 4 + 3][k] = v.w;
        }
        __syncthreads();
#pragma unroll
        for (int hh = 0; hh < 32; hh++)
            acc = fmaf(Wt[hh][tid], lm[h0 + hh], acc);
        __syncthreads();
    }
    g_l[b * HH + tid] = acc;
}

// ---------------------------------------------------------------------------
// GEMM: CTA = 64 rows x 128 cols (nh half), 256 thr = 8 warps (2m x 4n),
// warp tile 32x32 -> acc 32 regs -> 3 CTAs/SM (24 warps, 6/SMSP).
// bf16 split-3 mma.sync, TERM-MAJOR ordering (RAW reuse distance 8).
// 3-stage cp.async ring over 8 K-chunks of 32, 1 sync per chunk.
// Stage = [Ahi 4KB | Alo 4KB | Bhi 8KB | Blo 8KB] = 24KB.
// ---------------------------------------------------------------------------
constexpr uint32_t STG = 24576;
constexpr uint32_t GEMM_SMEM = 3 * STG;  // 72KB -> 3 CTAs/SM

__global__ void __launch_bounds__(256, 3) gemm_kernel(const float* __restrict__ Vv) {
    extern __shared__ __align__(1024) char smem[];
    __shared__ float vsm[128];
    __shared__ float s_red[4][64];

    const uint32_t sb = smem_u32(smem);
    const int tid = threadIdx.x;
    const int lane = tid & 31;
    const int wid = tid >> 5;
    const int wm = wid & 1;       // 2 m-warps x 32 rows
    const int wn = wid >> 1;      // 4 n-warps x 32 cols
    const int m = blockIdx.x;     // 64-row tile
    const int nh = blockIdx.y;

    if (tid < 128) vsm[tid] = Vv[nh * 128 + tid];

    float acc[2][4][4];
#pragma unroll
    for (int i = 0; i < 2; i++)
#pragma unroll
        for (int j = 0; j < 4; j++)
#pragma unroll
            for (int k = 0; k < 4; k++) acc[i][j][k] = 0.0f;

    // stage loader: A = half of a conv 128-tile (4KB hi + 4KB lo), B = 16KB
    auto stage = [&](int kc, uint32_t sbase) {
        const char* xb = g_Xc + ((size_t)(m >> 1) * NCH + kc) * CHUNK_BYTES
                       + (m & 1) * 4096;
        const char* us = g_Uc + ((size_t)nh * NCH + kc) * CHUNK_BYTES;
        uint32_t o1 = (uint32_t)tid * 16u;           // 4KB / 256 thr
        CPA16(sbase + o1,         xb + o1);          // A hi
        CPA16(sbase + 4096u + o1, xb + 8192 + o1);   // A lo
        uint32_t o2 = (uint32_t)tid * 64u;           // 16KB / 256 thr
        uint32_t d2 = sbase + 8192u + o2;
        CPA16(d2 + 0u,  us + o2);      CPA16(d2 + 16u, us + o2 + 16);
        CPA16(d2 + 32u, us + o2 + 32); CPA16(d2 + 48u, us + o2 + 48);
        asm volatile("cp.async.commit_group;");
    };
    stage(0, sb);
    stage(1, sb + STG);

    // ldmatrix lane addressing (tiled128)
    const uint32_t lb = (uint32_t)((lane & 7) * 16);
    const uint32_t ab1 = (uint32_t)((lane >> 3) & 1);
    const uint32_t ab2 = (uint32_t)(lane >> 4);

    for (int kc = 0; kc < NCH; kc++) {
        if (kc < NCH - 1) asm volatile("cp.async.wait_group 1;");
        else              asm volatile("cp.async.wait_group 0;");
        __syncthreads();
        if (kc + 2 < NCH) stage(kc + 2, sb + (uint32_t)((kc + 2) % 3) * STG);

        const uint32_t cur = sb + (uint32_t)(kc % 3) * STG;

#pragma unroll
        for (int k0 = 0; k0 < 2; k0++) {
            const uint32_t kg = (uint32_t)(k0 * 2);

            uint32_t Ahi[2][4], Alo[2][4];
#pragma unroll
            for (int mt = 0; mt < 2; mt++) {
                uint32_t tix = ((uint32_t)(wm * 4 + mt * 2) + ab1) * 4 + kg + ab2;
                uint32_t addr = cur + tix * 128u + lb;
                ldsm4(Ahi[mt], addr);
                ldsm4(Alo[mt], addr + 4096u);
            }
            uint32_t Bhi[2][4], Blo[2][4];
#pragma unroll
            for (int ntp = 0; ntp < 2; ntp++) {
                uint32_t tix = ((uint32_t)(wn * 4 + ntp * 2) + ab2) * 4 + kg + ab1;
                uint32_t addr = cur + 8192u + tix * 128u + lb;
                ldsm4(Bhi[ntp], addr);
                ldsm4(Blo[ntp], addr + 8192u);
            }

            // term-major: 8 independent MMAs per term (reuse distance 8)
#pragma unroll
            for (int mt = 0; mt < 2; mt++)
#pragma unroll
                for (int ntp = 0; ntp < 2; ntp++)
#pragma unroll
                    for (int sub = 0; sub < 2; sub++)
                        mma_bf16(acc[mt][ntp * 2 + sub], Ahi[mt],
                                 Bhi[ntp][sub * 2], Bhi[ntp][sub * 2 + 1]);
#pragma unroll
            for (int mt = 0; mt < 2; mt++)
#pragma unroll
                for (int ntp = 0; ntp < 2; ntp++)
#pragma unroll
                    for (int sub = 0; sub < 2; sub++)
                        mma_bf16(acc[mt][ntp * 2 + sub], Ahi[mt],
                                 Blo[ntp][sub * 2], Blo[ntp][sub * 2 + 1]);
#pragma unroll
            for (int mt = 0; mt < 2; mt++)
#pragma unroll
                for (int ntp = 0; ntp < 2; ntp++)
#pragma unroll
                    for (int sub = 0; sub < 2; sub++)
                        mma_bf16(acc[mt][ntp * 2 + sub], Alo[mt],
                                 Bhi[ntp][sub * 2], Bhi[ntp][sub * 2 + 1]);
        }
    }

    // Epilogue: per row, sum over this warp's 32 cols of V[n]*tanh(acc+l)
#pragma unroll
    for (int mt = 0; mt < 2; mt++) {
#pragma unroll
        for (int rh = 0; rh < 2; rh++) {
            int rowl = wm * 32 + mt * 16 + rh * 8 + (lane >> 2);
            int rowg = m * 64 + rowl;
            const float* lr = g_l + (rowg / SS) * HH + nh * 128;
            float s = 0.0f;
#pragma unroll
            for (int nt = 0; nt < 4; nt++) {
#pragma unroll
                for (int cl = 0; cl < 2; cl++) {
                    int col = wn * 32 + nt * 8 + (lane & 3) * 2 + cl;
                    float v = acc[mt][nt][rh * 2 + cl] + __ldg(lr + col);
                    s = fmaf(vsm[col], tanh_fma(v), s);
                }
            }
            s += __shfl_xor_sync(0xffffffffu, s, 1);
            s += __shfl_xor_sync(0xffffffffu, s, 2);
            if ((lane & 3) == 0) s_red[wn][rowl] = s;
        }
    }
    __syncthreads();
    if (tid < 64)
        g_sc[nh * MROWS + m * 64 + tid] =
            (s_red[0][tid] + s_red[1][tid]) + (s_red[2][tid] + s_red[3][tid]);
}

// ---------------------------------------------------------------------------
// softmax over S + pooled + final projection
// ---------------------------------------------------------------------------
__global__ void __launch_bounds__(256) pool_kernel(const float* __restrict__ X,
                                                   const float* __restrict__ MW,
                                                   const float* __restrict__ Mb,
                                                   float* __restrict__ out) {
    __shared__ float sal[SS];
    __shared__ float red[8];
    __shared__ float4 red4[8];

    const int b = blockIdx.x;
    const int tid = threadIdx.x;
    const int lane = tid & 31;
    const int w = tid >> 5;

    float v;
    if (tid < SS) {
        int idx = b * SS + tid;
        v = g_sc[idx] + g_sc[MROWS + idx];
    } else {
        v = __int_as_float(0xff800000);
    }
    float mx = v;
#pragma unroll
    for (int o = 16; o; o >>= 1) mx = fmaxf(mx, __shfl_xor_sync(0xffffffffu, mx, o));
    if (lane == 0) red[w] = mx;
    __syncthreads();
    float bm = red[0];
#pragma unroll
    for (int i = 1; i < 8; i++) bm = fmaxf(bm, red[i]);

    float e = (tid < SS) ? __expf(v - bm) : 0.0f;
    float s = e;
#pragma unroll
    for (int o = 16; o; o >>= 1) s += __shfl_xor_sync(0xffffffffu, s, o);
    __syncthreads();
    if (lane == 0) red[w] = s;
    __syncthreads();
    float bs = 0.0f;
#pragma unroll
    for (int i = 0; i < 8; i++) bs += red[i];

    if (tid < SS) sal[tid] = e / bs;
    __syncthreads();

    const float* Xb = X + (size_t)b * SS * HH + tid;
    float acc = 0.0f;
#pragma unroll 8
    for (int sdx = 0; sdx < SS; sdx++)
        acc = fmaf(sal[sdx], Xb[(size_t)sdx * HH], acc);

    float4 p;
    p.x = acc * MW[0 * HH + tid];
    p.y = acc * MW[1 * HH + tid];
    p.z = acc * MW[2 * HH + tid];
    p.w = acc * MW[3 * HH + tid];
#pragma unroll
    for (int o = 16; o; o >>= 1) {
        p.x += __shfl_xor_sync(0xffffffffu, p.x, o);
        p.y += __shfl_xor_sync(0xffffffffu, p.y, o);
        p.z += __shfl_xor_sync(0xffffffffu, p.z, o);
        p.w += __shfl_xor_sync(0xffffffffu, p.w, o);
    }
    if (lane == 0) red4[w] = p;
    __syncthreads();
    if (tid == 0) {
        float4 t = red4[0];
#pragma unroll
        for (int i = 1; i < 8; i++) {
            t.x += red4[i].x; t.y += red4[i].y; t.z += red4[i].z; t.w += red4[i].w;
        }
        out[b * 4 + 0] = t.x + Mb[0];
        out[b * 4 + 1] = t.y + Mb[1];
        out[b * 4 + 2] = t.z + Mb[2];
        out[b * 4 + 3] = t.w + Mb[3];
    }
}

// ---------------------------------------------------------------------------
extern "C" void kernel_launch(void* const* d_in, const int* in_sizes, int n_in,
                              void* d_out, int out_size) {
    const float* X     = (const float*)d_in[0];
    const float* lastm = (const float*)d_in[1];
    const float* U     = (const float*)d_in[2];
    const float* W     = (const float*)d_in[3];
    const float* Vv    = (const float*)d_in[4];
    const float* MW    = (const float*)d_in[5];
    const float* Mb    = (const float*)d_in[6];
    float* out = (float*)d_out;

    char *xc, *uc;
    cudaGetSymbolAddress((void**)&xc, g_Xc);
    cudaGetSymbolAddress((void**)&uc, g_Uc);

    cudaFuncSetAttribute(gemm_kernel, cudaFuncAttributeMaxDynamicSharedMemorySize, GEMM_SMEM);

    conv_kernel<<<2 * NCH, 128>>>(U, uc);               // U -> tiled128
    conv_kernel<<<(MT64 / 2) * NCH, 128>>>(X, xc);      // X -> tiled128
    l_kernel<<<BB, 256>>>(lastm, W);
    gemm_kernel<<<dim3(MT64, 2), 256, GEMM_SMEM>>>(Vv);
    pool_kernel<<<BB, 256>>>(X, MW, Mb, out);
}